// round 2
// baseline (speedup 1.0000x reference)
#include <cuda_runtime.h>
#include <cstdint>

#define S_TOTAL 524288
#define N_PROP 6
#define N_OBJ 8

// out layout: action_probs (2, S, 3) then p_values (2, 28, S)
__global__ __launch_bounds__(256)
void ump_kernel(const float* __restrict__ x,
                const float* __restrict__ action,
                const unsigned char* __restrict__ mask,
                const float* __restrict__ pb,
                float* __restrict__ out)
{
    int s = blockIdx.x * blockDim.x + threadIdx.x;
    if (s >= S_TOTAL) return;

    const float* row = x + (size_t)s * (N_OBJ * N_PROP);

    // load props 0,1 of each of the 8 objects (8B-aligned float2, stride 24B)
    float2 v[N_OBJ];
#pragma unroll
    for (int j = 0; j < N_OBJ; j++) {
        v[j] = *reinterpret_cast<const float2*>(row + j * N_PROP);
    }

    // existence
    bool agent_exist = v[0].x > 0.8f;
    bool enemy_exist = true;
#pragma unroll
    for (int j = 1; j < N_OBJ; j++) enemy_exist = enemy_exist && (v[j].y > 0.8f);
    bool m0 = mask[0] != 0;
    bool m1 = mask[1] != 0;
    bool exist_satisfy = (agent_exist == m0) && (enemy_exist == m1);

    // pred bounds: [[lb0,ub0],[lb1,ub1]]
    float lb0 = pb[0], ub0 = pb[1], lb1 = pb[2], ub1 = pb[3];

    float d[7][2];
    bool any_sat = false;
#pragma unroll
    for (int p = 0; p < 7; p++) {
        float d0 = fabsf(v[0].x - v[p + 1].x);
        float d1 = fabsf(v[0].y - v[p + 1].y);
        d[p][0] = d0;
        d[p][1] = d1;
        any_sat = any_sat || (d0 >= lb0 && d0 <= ub0 && d0 >= lb1 && d0 <= ub1);
        any_sat = any_sat || (d1 >= lb0 && d1 <= ub0 && d1 >= lb1 && d1 <= ub1);
    }
    bool satisfies = any_sat && exist_satisfy;

    // action_norm
    float a0 = action[0], a1 = action[1], a2 = action[2];
    float an0 = a0 / (a0 + 1e-20f);
    float an1 = a1 / (a1 + 1e-20f);
    float an2 = a2 / (a2 + 1e-20f);
    float w0 = satisfies ? an0 : 0.0f;
    float w1 = satisfies ? an1 : 0.0f;
    float w2 = satisfies ? an2 : 0.0f;

    // action_probs: [t, s, c], t in {0,1} — identical for both types
    const size_t S = (size_t)S_TOTAL;
    {
        size_t base0 = (size_t)s * 3;        // t=0
        size_t base1 = 3 * S + (size_t)s * 3; // t=1
        out[base0 + 0] = w0; out[base0 + 1] = w1; out[base0 + 2] = w2;
        out[base1 + 0] = w0; out[base1 + 1] = w1; out[base1 + 2] = w2;
    }

    // p_values: offset 6S, shape (2, 28, S); row = p*4 + k*2 + j, value d[p][k]
    float* __restrict__ pv = out + 6 * S;
#pragma unroll
    for (int p = 0; p < 7; p++) {
#pragma unroll
        for (int k = 0; k < 2; k++) {
            float val = d[p][k];
            size_t r = (size_t)(p * 4 + k * 2);
            pv[(r + 0) * S + s] = val;
            pv[(r + 1) * S + s] = val;
            pv[(r + 0 + 28) * S + s] = val;
            pv[(r + 1 + 28) * S + s] = val;
        }
    }
}

extern "C" void kernel_launch(void* const* d_in, const int* in_sizes, int n_in,
                              void* d_out, int out_size)
{
    const float* x = (const float*)d_in[0];
    const float* action = (const float*)d_in[1];
    const unsigned char* mask = (const unsigned char*)d_in[2];
    const float* pb = (const float*)d_in[3];
    float* out = (float*)d_out;

    int threads = 256;
    int blocks = (S_TOTAL + threads - 1) / threads;
    ump_kernel<<<blocks, threads>>>(x, action, mask, pb, out);
}